// round 1
// baseline (speedup 1.0000x reference)
#include <cuda_runtime.h>
#include <cstdint>

// Problem constants
// B=8, C=16, H=W=64, O=32, K=3, S=1, P=1, G=8, D=144, K-dim = D*G = 1152
// grid = linspace(-2,2,8), h = 4/7
// exp(-((v-g)/h)^2) = 2^(-u^2),  u = v*C1 + c2[g],  C1 = sqrt(log2 e)*7/4

#define C1F 2.1019642153762872f

__device__ __constant__ float C2F[8] = {
     4.2039284307525744f,  3.0028060219661250f,  1.8016836131796750f,  0.6005612043932250f,
    -0.6005612043932250f, -1.8016836131796750f, -3.0028060219661250f, -4.2039284307525744f
};

// Scratch (allocation-free rule: __device__ globals)
__device__ __align__(16) float  g_Wsum[32 * 1152];          // 147 KB
__device__ __align__(16) float  g_conv[8 * 32 * 64 * 64];   // 4 MB pre-BN output
__device__ float2 g_bn[32];                                  // per-channel scale/shift

// ---------------------------------------------------------------------------
// helpers
// ---------------------------------------------------------------------------
__device__ __forceinline__ float ex2(float m) {
    float r; asm("ex2.approx.f32 %0, %1;" : "=f"(r) : "f"(m)); return r;
}
__device__ __forceinline__ unsigned long long pk(float lo, float hi) {
    unsigned long long r;
    asm("mov.b64 %0, {%1, %2};" : "=l"(r) : "f"(lo), "f"(hi));
    return r;
}
__device__ __forceinline__ float hsum2(unsigned long long v) {
    float lo, hi;
    asm("mov.b64 {%0, %1}, %2;" : "=f"(lo), "=f"(hi) : "l"(v));
    return lo + hi;
}

// one (o, d) step: 8 MACs as 4 packed f32x2 FMAs; w read from smem (broadcast)
__device__ __forceinline__ void dot_step(unsigned long long& a0, unsigned long long& a1,
                                         unsigned long long b01, unsigned long long b23,
                                         unsigned long long b45, unsigned long long b67,
                                         unsigned saddr) {
    asm volatile(
        "{\n\t"
        ".reg .b32 w0, w1, w2, w3, w4, w5, w6, w7;\n\t"
        ".reg .b64 q01, q23, q45, q67;\n\t"
        "ld.shared.v4.b32 {w0, w1, w2, w3}, [%2];\n\t"
        "ld.shared.v4.b32 {w4, w5, w6, w7}, [%2+16];\n\t"
        "mov.b64 q01, {w0, w1};\n\t"
        "mov.b64 q23, {w2, w3};\n\t"
        "mov.b64 q45, {w4, w5};\n\t"
        "mov.b64 q67, {w6, w7};\n\t"
        "fma.rn.f32x2 %0, %3, q01, %0;\n\t"
        "fma.rn.f32x2 %1, %4, q23, %1;\n\t"
        "fma.rn.f32x2 %0, %5, q45, %0;\n\t"
        "fma.rn.f32x2 %1, %6, q67, %1;\n\t"
        "}"
        : "+l"(a0), "+l"(a1)
        : "r"(saddr), "l"(b01), "l"(b23), "l"(b45), "l"(b67));
}

// ---------------------------------------------------------------------------
// Kernel 1: Wsum[o,k] = sum_d W[o,d,k]   (W: [32,144,1152])
// ---------------------------------------------------------------------------
__global__ void __launch_bounds__(256) wsum_k(const float* __restrict__ W) {
    int idx = blockIdx.x * 256 + threadIdx.x;   // 0..36863 exactly
    int o = idx / 1152;
    int k = idx - o * 1152;
    const float* p = W + (size_t)o * 165888 + k;
    float a0 = 0.f, a1 = 0.f, a2 = 0.f, a3 = 0.f;
#pragma unroll
    for (int d = 0; d < 144; d += 4) {
        a0 += p[(d + 0) * 1152];
        a1 += p[(d + 1) * 1152];
        a2 += p[(d + 2) * 1152];
        a3 += p[(d + 3) * 1152];
    }
    g_Wsum[idx] = (a0 + a1) + (a2 + a3);
}

// ---------------------------------------------------------------------------
// Kernel 2: fused unfold + RBF basis + einsum.
// CTA = 256 threads = 4 output rows x 64 cols of one batch image.
// smem: Wsum (147456 B) + padded x tile 16c x 6rows x 66cols (25344 B)
// Each thread: 1 pixel, all 32 output channels, acc packed over g-pairs.
// ---------------------------------------------------------------------------
#define SMEM_BYTES (147456 + 25344)

__global__ void __launch_bounds__(256) kan_conv(const float* __restrict__ x) {
    extern __shared__ float sm[];
    float* sw = sm;                 // 32*1152 floats
    float* sx = sm + 32 * 1152;     // 16*6*66 floats

    const int tid  = threadIdx.x;
    const int tile = blockIdx.x;        // 0..127
    const int b    = tile >> 4;
    const int i0   = (tile & 15) << 2;

    // stage Wsum (float4, coalesced; resident in L2 after kernel 1)
    {
        const float4* gw4 = (const float4*)g_Wsum;
        float4* sw4 = (float4*)sw;
#pragma unroll 1
        for (int idx = tid; idx < 9216; idx += 256) sw4[idx] = gw4[idx];
    }
    // stage x tile with zero padding: rows i0-1 .. i0+4, cols -1 .. 64
#pragma unroll 1
    for (int idx = tid; idx < 16 * 6 * 66; idx += 256) {
        int c   = idx / 396;
        int rem = idx - c * 396;
        int r   = rem / 66;
        int col = rem - r * 66;
        int y  = i0 - 1 + r;
        int xx = col - 1;
        float v = 0.f;
        if ((unsigned)y < 64u && (unsigned)xx < 64u)
            v = x[(((b * 16 + c) << 6) + y) * 64 + xx];
        sx[idx] = v;
    }
    __syncthreads();

    const int li = tid >> 6;
    const int j  = tid & 63;

    unsigned long long accA[32], accB[32];
#pragma unroll
    for (int o = 0; o < 32; ++o) { accA[o] = 0ull; accB[o] = 0ull; }

    unsigned wptr = (unsigned)__cvta_generic_to_shared(sw);

#pragma unroll 1
    for (int c = 0; c < 16; ++c) {
        const float* xc = sx + c * 396 + li * 66 + j;
#pragma unroll 1
        for (int kh = 0; kh < 3; ++kh) {
            const float* xr = xc + kh * 66;
#pragma unroll
            for (int kw = 0; kw < 3; ++kw) {
                float v = xr[kw];
                float bb[8];
#pragma unroll
                for (int g = 0; g < 8; ++g) {
                    float u = fmaf(v, C1F, C2F[g]);
                    bb[g] = ex2(__fmul_rn(u, -u));   // exp(-((v-grid)/h)^2)
                }
                unsigned long long b01 = pk(bb[0], bb[1]);
                unsigned long long b23 = pk(bb[2], bb[3]);
                unsigned long long b45 = pk(bb[4], bb[5]);
                unsigned long long b67 = pk(bb[6], bb[7]);
#pragma unroll
                for (int o = 0; o < 32; ++o)
                    dot_step(accA[o], accB[o], b01, b23, b45, b67, wptr + (unsigned)o * 4608u);
                wptr += 32u;
            }
        }
    }

    // write pre-BN conv output, layout [B][O][64][64]
    float* outp = g_conv + ((size_t)b << 17) + (((i0 + li) << 6) + j);
#pragma unroll
    for (int o = 0; o < 32; ++o)
        outp[(size_t)o << 12] = hsum2(accA[o]) + hsum2(accB[o]);
}

// ---------------------------------------------------------------------------
// Kernel 3: per-channel batch stats -> scale/shift (deterministic tree reduce)
// ---------------------------------------------------------------------------
__global__ void __launch_bounds__(256) bn_stats(const float* __restrict__ gamma,
                                                const float* __restrict__ beta) {
    const int o = blockIdx.x, tid = threadIdx.x;
    float s = 0.f, q = 0.f;
    const float4* base = (const float4*)g_conv + ((size_t)o << 10);
#pragma unroll
    for (int b = 0; b < 8; ++b) {
        const float4* p = base + ((size_t)b << 15);
#pragma unroll
        for (int t = 0; t < 4; ++t) {
            float4 v = p[tid + t * 256];
            s += (v.x + v.y) + (v.z + v.w);
            q = fmaf(v.x, v.x, q); q = fmaf(v.y, v.y, q);
            q = fmaf(v.z, v.z, q); q = fmaf(v.w, v.w, q);
        }
    }
#pragma unroll
    for (int off = 16; off; off >>= 1) {
        s += __shfl_xor_sync(0xFFFFFFFFu, s, off);
        q += __shfl_xor_sync(0xFFFFFFFFu, q, off);
    }
    __shared__ float ss[8], sq[8];
    int w = tid >> 5, l = tid & 31;
    if (l == 0) { ss[w] = s; sq[w] = q; }
    __syncthreads();
    if (tid == 0) {
        float S = 0.f, Q = 0.f;
#pragma unroll
        for (int k = 0; k < 8; ++k) { S += ss[k]; Q += sq[k]; }
        float mean = S * (1.f / 32768.f);
        float var  = Q * (1.f / 32768.f) - mean * mean;
        float sc = gamma[o] * rsqrtf(var + 1e-5f);
        g_bn[o] = make_float2(sc, fmaf(-mean, sc, beta[o]));
    }
}

// ---------------------------------------------------------------------------
// Kernel 4: apply BN (elementwise, float4)
// ---------------------------------------------------------------------------
__global__ void __launch_bounds__(256) bn_apply(float* __restrict__ out) {
    int idx = blockIdx.x * 256 + threadIdx.x;   // 0..262143 float4
    int o = (idx >> 10) & 31;
    float2 st = g_bn[o];
    float4 v = ((const float4*)g_conv)[idx];
    v.x = fmaf(v.x, st.x, st.y);
    v.y = fmaf(v.y, st.x, st.y);
    v.z = fmaf(v.z, st.x, st.y);
    v.w = fmaf(v.w, st.x, st.y);
    ((float4*)out)[idx] = v;
}

// ---------------------------------------------------------------------------
extern "C" void kernel_launch(void* const* d_in, const int* in_sizes, int n_in,
                              void* d_out, int out_size) {
    const float* x     = (const float*)d_in[0];
    const float* W     = (const float*)d_in[1];
    const float* gamma = (const float*)d_in[2];
    const float* beta  = (const float*)d_in[3];
    float* out = (float*)d_out;

    cudaFuncSetAttribute(kan_conv, cudaFuncAttributeMaxDynamicSharedMemorySize, SMEM_BYTES);

    wsum_k  <<<144, 256>>>(W);
    kan_conv<<<128, 256, SMEM_BYTES>>>(x);
    bn_stats<<<32, 256>>>(gamma, beta);
    bn_apply<<<1024, 256>>>(out);
}

// round 3
// speedup vs baseline: 2.1059x; 2.1059x over previous
#include <cuda_runtime.h>
#include <cuda_bf16.h>
#include <cstdint>

// Problem: B=8, C=16, H=W=64, O=32, K=3, S=1, P=1, G=8, D=144, Kdim=D*G=1152
// basis(v,g) = exp(-((v-grid_g)/h)^2) = ex2(-u^2), u = v*C1 + C2[g]
// C1 = sqrt(log2 e)*7/4  (h = 4/7 folded in)
#define C1F 2.1019642153762872f

__device__ __constant__ float C2F[8] = {
     4.2039284307525744f,  3.0028060219661250f,  1.8016836131796750f,  0.6005612043932250f,
    -0.6005612043932250f, -1.8016836131796750f, -3.0028060219661250f, -4.2039284307525744f
};

// Scratch (__device__ globals; no allocation allowed)
// Wsum packed as bf16 hi/lo in mma.sync B-fragment layout:
// byte offset = (((kc*2 + sel)*2 + hi4)*32 + o)*16 + s2*4 + half*2
//   kc = k/16 (0..71), sel = 0 hi /1 lo, s = (k%16)/2, hi4 = s>>2, s2 = s&3, half = k&1
__device__ __align__(16) unsigned char g_Wfrag[147456];
__device__ __align__(16) float g_conv[8 * 32 * 64 * 64];   // pre-BN output, 4MB
__device__ float2 g_bn[32];

// ---------------------------------------------------------------------------
// helpers
// ---------------------------------------------------------------------------
__device__ __forceinline__ float ex2f(float m) {
    float r; asm("ex2.approx.f32 %0, %1;" : "=f"(r) : "f"(m)); return r;
}
__device__ __forceinline__ uint32_t pack_hi(float b0, float b1) {
    // bf16 truncation of both; low half = b0 (lower k index)
    uint32_t r, u0 = __float_as_uint(b0), u1 = __float_as_uint(b1);
    asm("prmt.b32 %0, %1, %2, 0x7632;" : "=r"(r) : "r"(u0), "r"(u1));
    return r;
}
__device__ __forceinline__ uint32_t pack_lo(float b0, float b1) {
    float l0 = b0 - __uint_as_float(__float_as_uint(b0) & 0xFFFF0000u);
    float l1 = b1 - __uint_as_float(__float_as_uint(b1) & 0xFFFF0000u);
    uint32_t r;
    asm("cvt.rn.bf16x2.f32 %0, %1, %2;" : "=r"(r) : "f"(l1), "f"(l0));
    return r;
}
__device__ __forceinline__ void mma16816(float* c, const uint32_t* a, const uint32_t* b) {
    asm volatile(
        "mma.sync.aligned.m16n8k16.row.col.f32.bf16.bf16.f32 "
        "{%0,%1,%2,%3}, {%4,%5,%6,%7}, {%8,%9}, {%0,%1,%2,%3};"
        : "+f"(c[0]), "+f"(c[1]), "+f"(c[2]), "+f"(c[3])
        : "r"(a[0]), "r"(a[1]), "r"(a[2]), "r"(a[3]), "r"(b[0]), "r"(b[1]));
}
__device__ __forceinline__ void cp16(uint32_t daddr, const void* src) {
    asm volatile("cp.async.cg.shared.global [%0], [%1], 16;"
                 :: "r"(daddr), "l"(src) : "memory");
}
__device__ __forceinline__ uint32_t smem_u32(const void* p) {
    uint32_t a;
    asm("{ .reg .u64 t; cvta.to.shared.u64 t, %1; cvt.u32.u64 %0, t; }" : "=r"(a) : "l"(p));
    return a;
}

// ---------------------------------------------------------------------------
// Kernel 1: Wsum[o,k] = sum_d W[o,d,k]; split fp32 -> bf16 hi(trunc)+lo(rn);
// store into B-fragment layout for mma.sync.
// ---------------------------------------------------------------------------
__global__ void __launch_bounds__(256) wsum_k(const float* __restrict__ W) {
    int idx = blockIdx.x * 256 + threadIdx.x;   // 144*256 = 36864 exactly
    int o = idx / 1152;
    int k = idx - o * 1152;
    const float* p = W + (size_t)o * 165888 + k;
    float a0 = 0.f, a1 = 0.f, a2 = 0.f, a3 = 0.f;
#pragma unroll
    for (int d = 0; d < 144; d += 4) {
        a0 += p[(d + 0) * 1152];
        a1 += p[(d + 1) * 1152];
        a2 += p[(d + 2) * 1152];
        a3 += p[(d + 3) * 1152];
    }
    float s = (a0 + a1) + (a2 + a3);

    uint32_t sb = __float_as_uint(s);
    unsigned short hib = (unsigned short)(sb >> 16);            // bf16 hi = truncation
    float hif = __uint_as_float(sb & 0xFFFF0000u);
    __nv_bfloat16 lo = __float2bfloat16(s - hif);               // exact residual -> rn

    int kc   = k >> 4;
    int kl   = k & 15;
    int slot = kl >> 1;
    int half = kl & 1;
    int base = (((kc * 2 + 0) * 2 + (slot >> 2)) * 32 + o) * 16 + (slot & 3) * 4 + half * 2;
    *(unsigned short*)(g_Wfrag + base)        = hib;
    *(unsigned short*)(g_Wfrag + base + 1024) = *(unsigned short*)&lo;  // sel=1 offset
}

// ---------------------------------------------------------------------------
// Kernel 2: fused unfold + RBF basis + bf16-split warp-level MMA.
// CTA = 256 threads (8 warps) = 4 rows x 64 cols of one image.
// Warp w: pixel row w/2, cols (w&1)*32 .. +31 (32 pixels x 32 channels).
// 72 k-chunks of 16 (2 d-values x 8 grids); 24 mma per chunk per warp.
// ---------------------------------------------------------------------------
#define SM_W 0
#define SM_X 147456
#define SMEM_TC (147456 + 25344)   // W frags + x tile (16c x 6r x 66c f32)

__global__ void __launch_bounds__(256, 1) kan_conv_mma(const float* __restrict__ x) {
    extern __shared__ char smem[];
    const uint32_t sb = smem_u32(smem);
    float* sx = (float*)(smem + SM_X);
    const uint32_t* swp = (const uint32_t*)(smem + SM_W);

    const int tid  = threadIdx.x;
    const int b    = blockIdx.x >> 4;
    const int r0   = (blockIdx.x & 15) << 2;

    // --- async copy of pre-packed Wsum into smem (2 groups: chunks 0-7, 8-71)
    const char* gw = (const char*)g_Wfrag;
#pragma unroll 1
    for (int i = tid; i < 1024; i += 256) cp16(sb + SM_W + i * 16, gw + i * 16);
    asm volatile("cp.async.commit_group;" ::: "memory");
#pragma unroll 1
    for (int i = 1024 + tid; i < 9216; i += 256) cp16(sb + SM_W + i * 16, gw + i * 16);
    asm volatile("cp.async.commit_group;" ::: "memory");

    // --- stage x tile: rows r0-1..r0+4 (6), cols -1..64 (66), 16 channels
#pragma unroll 1
    for (int idx = tid; idx < 16 * 6 * 66; idx += 256) {
        int c   = idx / 396;
        int rem = idx - c * 396;
        int r   = rem / 66;
        int col = rem - r * 66;
        int y  = r0 - 1 + r;
        int xx = col - 1;
        float v = 0.f;
        if ((unsigned)y < 64u && (unsigned)xx < 64u)
            v = x[(((b * 16 + c) << 6) + y) * 64 + xx];
        sx[idx] = v;
    }

    const int lane = tid & 31;
    const int w    = tid >> 5;
    const int prow = w >> 1;               // pixel row within 4-row tile
    const int pc   = (w & 1) << 5;         // pixel col base (0 or 32)
    const int qr   = lane >> 2;            // 0..7
    const int gp   = (lane & 3) << 1;      // grid pair base
    const float c2a = C2F[gp];
    const float c2b = C2F[gp + 1];

    float acc[2][4][4];
#pragma unroll
    for (int t = 0; t < 2; ++t)
#pragma unroll
        for (int n = 0; n < 4; ++n)
#pragma unroll
            for (int r = 0; r < 4; ++r) acc[t][n][r] = 0.f;

    // per-thread B base: word index = kc*512 + o*4 + s2, o = nt*8+qr, s2 = lane&3
    const uint32_t* wb = swp + (lane & 3) + (qr << 2);
    const float* xq = sx + (size_t)prow * 66 + pc + qr;

#pragma unroll 1
    for (int kc = 0; kc < 72; ++kc) {
        if (kc == 0) { asm volatile("cp.async.wait_group 1;" ::: "memory"); __syncthreads(); }
        if (kc == 8) { asm volatile("cp.async.wait_group 0;" ::: "memory"); __syncthreads(); }

        // ---- A fragments: basis for d0=2kc, d1=2kc+1, grids gp,gp+1, 4 pixel quads
        uint32_t Ah[8], Al[8];
#pragma unroll
        for (int dl = 0; dl < 2; ++dl) {
            int d  = 2 * kc + dl;
            int c  = d / 9;
            int r9 = d - c * 9;
            int kh = r9 / 3;
            int kw = r9 - kh * 3;
            const float* p = xq + c * 396 + kh * 66 + kw;
#pragma unroll
            for (int q = 0; q < 4; ++q) {
                float v  = p[q * 8];
                float ua = fmaf(v, C1F, c2a);
                float ba = ex2f(__fmul_rn(ua, -ua));
                float ub = fmaf(v, C1F, c2b);
                float bb = ex2f(__fmul_rn(ub, -ub));
                int ix = (q >> 1) * 4 + (q & 1) + 2 * dl;
                Ah[ix] = pack_hi(ba, bb);
                Al[ix] = pack_lo(ba, bb);
            }
        }

        // ---- B fragments (bank-conflict-free: bank == lane)
        const uint32_t* wk = wb + kc * 512;
        uint32_t Bh[8], Bl[8];
#pragma unroll
        for (int nt = 0; nt < 4; ++nt) {
            Bh[nt * 2]     = wk[nt * 32];
            Bh[nt * 2 + 1] = wk[nt * 32 + 128];
            Bl[nt * 2]     = wk[nt * 32 + 256];
            Bl[nt * 2 + 1] = wk[nt * 32 + 384];
        }

        // ---- 24 MMAs: hi*hi + lo*hi + hi*lo
#pragma unroll
        for (int t = 0; t < 2; ++t)
#pragma unroll
            for (int nt = 0; nt < 4; ++nt) {
                mma16816(acc[t][nt], Ah + t * 4, Bh + nt * 2);
                mma16816(acc[t][nt], Al + t * 4, Bh + nt * 2);
                mma16816(acc[t][nt], Ah + t * 4, Bl + nt * 2);
            }
    }

    // ---- epilogue: write pre-BN conv output [B][O][64][64]
    float* ob = g_conv + ((size_t)b << 17) + (size_t)(r0 + prow) * 64;
#pragma unroll
    for (int t = 0; t < 2; ++t) {
        int col0 = pc + (t << 4) + qr;
#pragma unroll
        for (int nt = 0; nt < 4; ++nt) {
            int o0 = nt * 8 + ((lane & 3) << 1);
            float* p0 = ob + ((size_t)o0 << 12);
            p0[col0]            = acc[t][nt][0];
            p0[4096 + col0]     = acc[t][nt][1];
            p0[col0 + 8]        = acc[t][nt][2];
            p0[4096 + col0 + 8] = acc[t][nt][3];
        }
    }
}

// ---------------------------------------------------------------------------
// Kernel 3: fused BN stats + apply. One CTA (1024 thr) per channel o.
// Pass 1: sum/sumsq over 32768 values; pass 2 re-reads (L2-hot) and writes out.
// ---------------------------------------------------------------------------
__global__ void __launch_bounds__(1024) bn_fused(const float* __restrict__ gamma,
                                                 const float* __restrict__ beta,
                                                 float* __restrict__ out) {
    const int o = blockIdx.x, tid = threadIdx.x;
    const float4* base = (const float4*)g_conv;
    float s = 0.f, q = 0.f;
#pragma unroll
    for (int t = 0; t < 8; ++t) {
        int idx = tid + t * 1024;              // 0..8191
        int bb  = idx >> 10;
        int i4  = idx & 1023;
        float4 v = base[(size_t)bb * 32768 + (size_t)o * 1024 + i4];
        s += (v.x + v.y) + (v.z + v.w);
        q = fmaf(v.x, v.x, q); q = fmaf(v.y, v.y, q);
        q = fmaf(v.z, v.z, q); q = fmaf(v.w, v.w, q);
    }
#pragma unroll
    for (int off = 16; off; off >>= 1) {
        s += __shfl_xor_sync(0xFFFFFFFFu, s, off);
        q += __shfl_xor_sync(0xFFFFFFFFu, q, off);
    }
    __shared__ float ss[32], sq[32];
    __shared__ float2 st;
    int wi = tid >> 5, l = tid & 31;
    if (l == 0) { ss[wi] = s; sq[wi] = q; }
    __syncthreads();
    if (wi == 0) {
        float S = (l < 32) ? ss[l] : 0.f;
        float Q = (l < 32) ? sq[l] : 0.f;
#pragma unroll
        for (int off = 16; off; off >>= 1) {
            S += __shfl_xor_sync(0xFFFFFFFFu, S, off);
            Q += __shfl_xor_sync(0xFFFFFFFFu, Q, off);
        }
        if (l == 0) {
            float mean = S * (1.f / 32768.f);
            float var  = Q * (1.f / 32768.f) - mean * mean;
            float sc = gamma[o] * rsqrtf(var + 1e-5f);
            st = make_float2(sc, fmaf(-mean, sc, beta[o]));
        }
    }
    __syncthreads();
    float2 bn = st;
    float4* outp = (float4*)out;
#pragma unroll
    for (int t = 0; t < 8; ++t) {
        int idx = tid + t * 1024;
        int bb  = idx >> 10;
        int i4  = idx & 1023;
        size_t a = (size_t)bb * 32768 + (size_t)o * 1024 + i4;
        float4 v = base[a];
        v.x = fmaf(v.x, bn.x, bn.y);
        v.y = fmaf(v.y, bn.x, bn.y);
        v.z = fmaf(v.z, bn.x, bn.y);
        v.w = fmaf(v.w, bn.x, bn.y);
        outp[a] = v;
    }
}

// ---------------------------------------------------------------------------
extern "C" void kernel_launch(void* const* d_in, const int* in_sizes, int n_in,
                              void* d_out, int out_size) {
    const float* x     = (const float*)d_in[0];
    const float* W     = (const float*)d_in[1];
    const float* gamma = (const float*)d_in[2];
    const float* beta  = (const float*)d_in[3];
    float* out = (float*)d_out;

    cudaFuncSetAttribute(kan_conv_mma, cudaFuncAttributeMaxDynamicSharedMemorySize, SMEM_TC);

    wsum_k      <<<144, 256>>>(W);
    kan_conv_mma<<<128, 256, SMEM_TC>>>(x);
    bn_fused    <<<32, 1024>>>(gamma, beta, out);
}

// round 4
// speedup vs baseline: 2.2908x; 1.0878x over previous
#include <cuda_runtime.h>
#include <cuda_bf16.h>
#include <cstdint>

// Problem: B=8, C=16, H=W=64, O=32, K=3, S=1, P=1, G=8, D=144, Kdim=D*G=1152
// basis(v,g) = exp(-((v-grid_g)/h)^2) = ex2(-u^2), u = v*C1 + C2[g]
#define C1F 2.1019642153762872f

__device__ __constant__ float C2F[8] = {
     4.2039284307525744f,  3.0028060219661250f,  1.8016836131796750f,  0.6005612043932250f,
    -0.6005612043932250f, -1.8016836131796750f, -3.0028060219661250f, -4.2039284307525744f
};

// Scratch (__device__ globals; no allocation allowed)
__device__ __align__(16) float g_Wpart[4 * 36864];          // phase-A partial sums
// W fragments: one 16B group per (kc, o, s2) = thread's {Bh0,Bh1,Bl0,Bl1}
// byte = kc*2048 + o*64 + s2*16 ; hi word at +hi4*4, lo word at +8+hi4*4, half at +half*2
__device__ __align__(16) unsigned char g_Wfrag[147456];
__device__ __align__(16) float g_conv[8 * 32 * 64 * 64];    // pre-BN output, 4MB
__device__ float2 g_part[256];                               // per-(o,b) sum/sumsq

// ---------------------------------------------------------------------------
// helpers
// ---------------------------------------------------------------------------
__device__ __forceinline__ float ex2f(float m) {
    float r; asm("ex2.approx.f32 %0, %1;" : "=f"(r) : "f"(m)); return r;
}
__device__ __forceinline__ uint32_t pack_hi(float b0, float b1) {
    uint32_t r, u0 = __float_as_uint(b0), u1 = __float_as_uint(b1);
    asm("prmt.b32 %0, %1, %2, 0x7632;" : "=r"(r) : "r"(u0), "r"(u1));
    return r;
}
__device__ __forceinline__ uint32_t pack_lo(float b0, float b1) {
    float l0 = b0 - __uint_as_float(__float_as_uint(b0) & 0xFFFF0000u);
    float l1 = b1 - __uint_as_float(__float_as_uint(b1) & 0xFFFF0000u);
    uint32_t r;
    asm("cvt.rn.bf16x2.f32 %0, %1, %2;" : "=r"(r) : "f"(l1), "f"(l0));
    return r;
}
__device__ __forceinline__ void mma16816(float* c, const uint32_t* a, uint32_t b0, uint32_t b1) {
    asm volatile(
        "mma.sync.aligned.m16n8k16.row.col.f32.bf16.bf16.f32 "
        "{%0,%1,%2,%3}, {%4,%5,%6,%7}, {%8,%9}, {%0,%1,%2,%3};"
        : "+f"(c[0]), "+f"(c[1]), "+f"(c[2]), "+f"(c[3])
        : "r"(a[0]), "r"(a[1]), "r"(a[2]), "r"(a[3]), "r"(b0), "r"(b1));
}
__device__ __forceinline__ uint32_t smem_u32(const void* p) {
    uint32_t a;
    asm("{ .reg .u64 t; cvta.to.shared.u64 t, %1; cvt.u32.u64 %0, t; }" : "=r"(a) : "l"(p));
    return a;
}

// ---------------------------------------------------------------------------
// Kernel 1a: partial Wsum over 36 d-values (4-way split for occupancy/MLP)
// ---------------------------------------------------------------------------
__global__ void __launch_bounds__(256) wsum_a(const float* __restrict__ W) {
    int bid = blockIdx.x;                       // 576
    int quarter = bid & 3;
    int idx = (bid >> 2) * 256 + threadIdx.x;   // 0..36863
    int o = idx / 1152;
    int k = idx - o * 1152;
    const float* p = W + (size_t)o * 165888 + (size_t)(quarter * 36) * 1152 + k;
    float a0 = 0.f, a1 = 0.f, a2 = 0.f, a3 = 0.f;
#pragma unroll
    for (int d = 0; d < 36; d += 4) {
        a0 += p[(d + 0) * 1152];
        a1 += p[(d + 1) * 1152];
        a2 += p[(d + 2) * 1152];
        a3 += p[(d + 3) * 1152];
    }
    g_Wpart[quarter * 36864 + idx] = (a0 + a1) + (a2 + a3);
}

// ---------------------------------------------------------------------------
// Kernel 1b: combine partials, split fp32 -> bf16 hi(trunc)+lo(rn), pack frags
// ---------------------------------------------------------------------------
__global__ void __launch_bounds__(256) wsum_b() {
    int idx = blockIdx.x * 256 + threadIdx.x;   // 144*256 = 36864
    int o = idx / 1152;
    int k = idx - o * 1152;
    float s = (g_Wpart[idx] + g_Wpart[36864 + idx])
            + (g_Wpart[2 * 36864 + idx] + g_Wpart[3 * 36864 + idx]);

    uint32_t sbits = __float_as_uint(s);
    unsigned short hib = (unsigned short)(sbits >> 16);
    float hif = __uint_as_float(sbits & 0xFFFF0000u);
    __nv_bfloat16 lo = __float2bfloat16(s - hif);

    int kc   = k >> 4;
    int kl   = k & 15;
    int slot = kl >> 1;
    int hi4  = slot >> 2;
    int s2   = slot & 3;
    int half = kl & 1;
    int base = kc * 2048 + o * 64 + s2 * 16;
    *(unsigned short*)(g_Wfrag + base + hi4 * 4 + half * 2)     = hib;
    *(unsigned short*)(g_Wfrag + base + 8 + hi4 * 4 + half * 2) = *(unsigned short*)&lo;
}

// ---------------------------------------------------------------------------
// Kernel 2: Phi-precompute + implicit-GEMM 3x3 conv via bf16-split mma.sync.
// CTA = 256 thr (8 warps) = 4 out-rows x 64 cols of one image, grid 128.
// Phi tile in smem: [c:16][xr:6][xc:66][h0 l0 h1 l1 h2 l2 h3 l3] (32B/elem).
// Each basis value computed ONCE per x element (9x reuse via shifted reads).
// W fragments streamed from L2 via per-thread LDG.128 double buffer.
// ---------------------------------------------------------------------------
#define PHI_R 2112                      // 66 * 32
#define PHI_C 12672                     // 6 * 2112
#define SMEM_PHI 202752                 // 16 * 12672

__global__ void __launch_bounds__(256, 1) kan_conv_mma(const float* __restrict__ x) {
    extern __shared__ char smem[];
    const uint32_t sb = smem_u32(smem);
    const int tid = threadIdx.x;
    const int b   = blockIdx.x >> 4;
    const int r0  = (blockIdx.x & 15) << 2;

    // ---- Phase 1: build Phi tile (rows r0-1..r0+4, cols -1..64, 16 ch) ----
#pragma unroll 1
    for (int idx = tid; idx < 6336; idx += 256) {
        int c   = idx / 396;
        int rem = idx - c * 396;
        int r   = rem / 66;
        int col = rem - r * 66;
        int y  = r0 - 1 + r;
        int xx = col - 1;
        float v = 0.f;
        if ((unsigned)y < 64u && (unsigned)xx < 64u)
            v = x[(((b * 16 + c) << 6) + y) * 64 + xx];
        float bb[8];
#pragma unroll
        for (int g = 0; g < 8; ++g) {
            float u = fmaf(v, C1F, C2F[g]);
            bb[g] = ex2f(__fmul_rn(u, -u));
        }
        uint32_t hw[4], lw[4];
#pragma unroll
        for (int i = 0; i < 4; ++i) {
            hw[i] = pack_hi(bb[2 * i], bb[2 * i + 1]);
            lw[i] = pack_lo(bb[2 * i], bb[2 * i + 1]);
        }
        uint32_t a = sb + c * PHI_C + r * PHI_R + col * 32;
        asm volatile("st.shared.v4.b32 [%0], {%1,%2,%3,%4};"
                     :: "r"(a), "r"(hw[0]), "r"(lw[0]), "r"(hw[1]), "r"(lw[1]) : "memory");
        asm volatile("st.shared.v4.b32 [%0+16], {%1,%2,%3,%4};"
                     :: "r"(a), "r"(hw[2]), "r"(lw[2]), "r"(hw[3]), "r"(lw[3]) : "memory");
    }
    __syncthreads();

    // ---- Phase 2: 72 k-chunks x 24 mma ----
    const int lane = tid & 31;
    const int w    = tid >> 5;
    const int prow = w >> 1;               // out-row within 4-row tile
    const int pc   = (w & 1) << 5;         // out-col base (0/32)
    const int qr   = lane >> 2;
    const int gp   = lane & 3;

    const uint32_t abase = sb + (uint32_t)prow * PHI_R + (uint32_t)(pc + qr) * 32 + (uint32_t)gp * 8;
    const uint4* wq = ((const uint4*)g_Wfrag) + lane;   // +nt*32 +kc*128

    float acc[2][4][4];
#pragma unroll
    for (int t = 0; t < 2; ++t)
#pragma unroll
        for (int n = 0; n < 4; ++n)
#pragma unroll
            for (int r = 0; r < 4; ++r) acc[t][n][r] = 0.f;

    uint4 Bc[4];
#pragma unroll
    for (int nt = 0; nt < 4; ++nt) Bc[nt] = __ldg(wq + nt * 32);

#pragma unroll 4
    for (int kc = 0; kc < 72; ++kc) {
        uint4 Bn[4];
        if (kc < 71) {
#pragma unroll
            for (int nt = 0; nt < 4; ++nt) Bn[nt] = __ldg(wq + (kc + 1) * 128 + nt * 32);
        } else {
#pragma unroll
            for (int nt = 0; nt < 4; ++nt) Bn[nt] = Bc[nt];
        }

        uint32_t Ah[8], Al[8];
#pragma unroll
        for (int dl = 0; dl < 2; ++dl) {
            int d  = 2 * kc + dl;
            int c  = d / 9;
            int r9 = d - 9 * c;
            int kh = r9 / 3;
            int kw = r9 - 3 * kh;
            uint32_t ta = abase + (uint32_t)(c * PHI_C + kh * PHI_R + kw * 32);
#pragma unroll
            for (int q = 0; q < 4; ++q) {
                uint32_t ah, al;
                asm("ld.shared.v2.b32 {%0,%1}, [%2];" : "=r"(ah), "=r"(al) : "r"(ta + q * 256));
                int ix = (q >> 1) * 4 + (q & 1) + 2 * dl;
                Ah[ix] = ah; Al[ix] = al;
            }
        }

#pragma unroll
        for (int t = 0; t < 2; ++t)
#pragma unroll
            for (int nt = 0; nt < 4; ++nt) {
                mma16816(acc[t][nt], Ah + t * 4, Bc[nt].x, Bc[nt].y);
                mma16816(acc[t][nt], Al + t * 4, Bc[nt].x, Bc[nt].y);
                mma16816(acc[t][nt], Ah + t * 4, Bc[nt].z, Bc[nt].w);
            }
#pragma unroll
        for (int nt = 0; nt < 4; ++nt) Bc[nt] = Bn[nt];
    }

    // ---- epilogue: write pre-BN conv output [B][O][64][64] ----
    float* ob = g_conv + ((size_t)b << 17) + (size_t)(r0 + prow) * 64;
#pragma unroll
    for (int t = 0; t < 2; ++t) {
        int col0 = pc + (t << 4) + qr;
#pragma unroll
        for (int nt = 0; nt < 4; ++nt) {
            int o0 = nt * 8 + (gp << 1);
            float* p0 = ob + ((size_t)o0 << 12);
            p0[col0]            = acc[t][nt][0];
            p0[4096 + col0]     = acc[t][nt][1];
            p0[col0 + 8]        = acc[t][nt][2];
            p0[4096 + col0 + 8] = acc[t][nt][3];
        }
    }
}

// ---------------------------------------------------------------------------
// Kernel 3a: BN partial stats. CTA = one (o, b) slice: 4096 floats.
// ---------------------------------------------------------------------------
__global__ void __launch_bounds__(256) bn_part() {
    const int o = blockIdx.x >> 3;
    const int bb = blockIdx.x & 7;
    const int tid = threadIdx.x;
    const float4* p = (const float4*)g_conv + (size_t)bb * 32768 + (size_t)o * 1024;
    float s = 0.f, q = 0.f;
#pragma unroll
    for (int t = 0; t < 4; ++t) {
        float4 v = p[tid + t * 256];
        s += (v.x + v.y) + (v.z + v.w);
        q = fmaf(v.x, v.x, q); q = fmaf(v.y, v.y, q);
        q = fmaf(v.z, v.z, q); q = fmaf(v.w, v.w, q);
    }
#pragma unroll
    for (int off = 16; off; off >>= 1) {
        s += __shfl_xor_sync(0xFFFFFFFFu, s, off);
        q += __shfl_xor_sync(0xFFFFFFFFu, q, off);
    }
    __shared__ float ss[8], sq[8];
    int wi = tid >> 5, l = tid & 31;
    if (l == 0) { ss[wi] = s; sq[wi] = q; }
    __syncthreads();
    if (tid == 0) {
        float S = 0.f, Q = 0.f;
#pragma unroll
        for (int k = 0; k < 8; ++k) { S += ss[k]; Q += sq[k]; }
        g_part[blockIdx.x] = make_float2(S, Q);
    }
}

// ---------------------------------------------------------------------------
// Kernel 3b: BN apply. CTA covers 256 float4 of one (b,o) plane quarter.
// o is constant per CTA; params computed deterministically from 8 partials.
// ---------------------------------------------------------------------------
__global__ void __launch_bounds__(256) bn_apply(const float* __restrict__ gamma,
                                                const float* __restrict__ beta,
                                                float* __restrict__ out) {
    const int bid = blockIdx.x;                 // 1024
    const int o = (bid >> 2) & 31;
    __shared__ float2 stp;
    if (threadIdx.x == 0) {
        float S = 0.f, Q = 0.f;
#pragma unroll
        for (int j = 0; j < 8; ++j) {
            float2 pq = g_part[o * 8 + j];
            S += pq.x; Q += pq.y;
        }
        float mean = S * (1.f / 32768.f);
        float var  = Q * (1.f / 32768.f) - mean * mean;
        float sc = gamma[o] * rsqrtf(var + 1e-5f);
        stp = make_float2(sc, fmaf(-mean, sc, beta[o]));
    }
    __syncthreads();
    float2 bn = stp;
    size_t idx = (size_t)bid * 256 + threadIdx.x;
    float4 v = ((const float4*)g_conv)[idx];
    v.x = fmaf(v.x, bn.x, bn.y);
    v.y = fmaf(v.y, bn.x, bn.y);
    v.z = fmaf(v.z, bn.x, bn.y);
    v.w = fmaf(v.w, bn.x, bn.y);
    ((float4*)out)[idx] = v;
}

// ---------------------------------------------------------------------------
extern "C" void kernel_launch(void* const* d_in, const int* in_sizes, int n_in,
                              void* d_out, int out_size) {
    const float* x     = (const float*)d_in[0];
    const float* W     = (const float*)d_in[1];
    const float* gamma = (const float*)d_in[2];
    const float* beta  = (const float*)d_in[3];
    float* out = (float*)d_out;

    cudaFuncSetAttribute(kan_conv_mma, cudaFuncAttributeMaxDynamicSharedMemorySize, SMEM_PHI);

    wsum_a      <<<576, 256>>>(W);
    wsum_b      <<<144, 256>>>();
    kan_conv_mma<<<128, 256, SMEM_PHI>>>(x);
    bn_part     <<<256, 256>>>();
    bn_apply    <<<1024, 256>>>(gamma, beta, out);
}